// round 5
// baseline (speedup 1.0000x reference)
#include <cuda_runtime.h>

// PureCascadedBitFFN: out[elem, j] = j-th bit (LSB=0) of
// k = ceil(distance[elem] - 0.5) (exact reduction of the sigmoid cascade).
//
// 128 MB f32 output: at the HBM/LTS streaming-write wall (~5.9 TB/s eff).
// R3/R4 showed store mapping + read dedup are all neutral -> only remaining
// lever is wave structure. This version is a persistent single-wave grid:
// 1184 CTAs (148 SMs x 8) grid-striding over 4096 tiles of 2048 quads,
// removing ~2.5 wave transitions and the ragged tail.
//
// Per tile: 256 threads x 8 coalesced 512B STG.128 bursts, __stcs
// evict-first, direct __ldg reads (read path proven non-contending in R4).

__global__ __launch_bounds__(256) void cascaded_bits_kernel(
    const float* __restrict__ dist,
    float4* __restrict__ out,
    int ntiles)
{
    const int tid = threadIdx.x;

    for (int tile = blockIdx.x; tile < ntiles; tile += gridDim.x) {
        const int base = tile * 2048 + tid;

        float r[8];
        #pragma unroll
        for (int i = 0; i < 8; i++)
            r[i] = __ldg(&dist[(base + i * 256) >> 2]);

        int k[8];
        #pragma unroll
        for (int i = 0; i < 8; i++)
            k[i] = __float2int_ru(r[i] - 0.5f);  // exact round-half-down

        #pragma unroll
        for (int i = 0; i < 8; i++) {
            const int q   = base + i * 256;
            const int bit = (q & 3) << 2;        // starting bit: 0,4,8,12
            float4 v;
            v.x = (float)((k[i] >> (bit + 0)) & 1);
            v.y = (float)((k[i] >> (bit + 1)) & 1);
            v.z = (float)((k[i] >> (bit + 2)) & 1);
            v.w = (float)((k[i] >> (bit + 3)) & 1);
            __stcs(&out[q], v);                  // streaming: evict-first in L2
        }
    }
}

extern "C" void kernel_launch(void* const* d_in, const int* in_sizes, int n_in,
                              void* d_out, int out_size)
{
    const float* dist = (const float*)d_in[0];
    float4* out = (float4*)d_out;

    int n_elems = in_sizes[0];            // 512*4096 = 2,097,152
    int nquads  = n_elems * 4;            // 8,388,608
    int ntiles  = nquads / 2048;          // 4096 (exact)

    // Single-wave persistent grid: 148 SMs x 8 CTAs (256 thr, 32 regs -> fits)
    int blocks = 148 * 8;                 // 1184
    if (blocks > ntiles) blocks = ntiles;

    cascaded_bits_kernel<<<blocks, 256>>>(dist, out, ntiles);
}